// round 1
// baseline (speedup 1.0000x reference)
#include <cuda_runtime.h>

#define NB   8      // batches per block
#define TT   512
#define HH   50
#define GG   200    // 4*H
#define NTHR 128

typedef unsigned long long u64;

// ---- packed f32x2 helpers (sm_103a FFMA2 path, PTX-only) ----
__device__ __forceinline__ u64 pack2(float x) {
    u64 r; asm("mov.b64 %0, {%1,%1};" : "=l"(r) : "f"(x)); return r;
}
__device__ __forceinline__ u64 fma2(u64 a, u64 b, u64 c) {
    u64 d; asm("fma.rn.f32x2 %0, %1, %2, %3;" : "=l"(d) : "l"(a), "l"(b), "l"(c)); return d;
}

// ---- activations: EX2/RCP based, ~1e-6 accurate ----
__device__ __forceinline__ float sigmoidf_(float x) {
    float e = __expf(-x);
    return __fdividef(1.f, 1.f + e);
}
__device__ __forceinline__ float tanhf_(float x) {
    float ax = fabsf(x);
    float e  = __expf(-2.f * ax);
    float t  = __fdividef(1.f - e, 1.f + e);
    return copysignf(t, x);
}

__global__ void __launch_bounds__(NTHR, 2)
lstm_fused(const float* __restrict__ x,    const float* __restrict__ W_ih,
           const float* __restrict__ W_hh, const float* __restrict__ b_ih,
           const float* __restrict__ b_hh, const float* __restrict__ fc_w,
           const float* __restrict__ fc_b, float* __restrict__ out)
{
    __shared__ __align__(16) float x_sh[TT][NB];   // 16 KB, x transposed [t][b]
    __shared__ __align__(16) float h_sh[HH][NB];   // hidden state, [k][b]
    __shared__ __align__(16) float g_sh[GG][12];   // gate preacts, padded rows (48B)

    const int tid = threadIdx.x;
    const int b0  = blockIdx.x * NB;

    // ---- stage x: global [b][t] (contiguous 16KB) -> shared [t][b] ----
    const float4* xg = reinterpret_cast<const float4*>(x + (size_t)b0 * TT);
    #pragma unroll
    for (int i = 0; i < (NB * TT / 4) / NTHR; i++) {   // 8 iters
        int idx = tid + i * NTHR;
        float4 v = xg[idx];
        int e  = idx * 4;
        int bb = e >> 9;          // / 512
        int t  = e & (TT - 1);
        x_sh[t + 0][bb] = v.x; x_sh[t + 1][bb] = v.y;
        x_sh[t + 2][bb] = v.z; x_sh[t + 3][bb] = v.w;
    }
    for (int i = tid; i < HH * NB; i += NTHR) (&h_sh[0][0])[i] = 0.f;

    // ---- per-thread setup: rows (tid, tid+100) of W_hh live in registers ----
    const bool act = (tid < 100);
    float w0[HH], w1[HH];
    u64 wx2_0 = 0, wx2_1 = 0, bi2_0 = 0, bi2_1 = 0;
    if (act) {
        #pragma unroll
        for (int k = 0; k < HH; k++) {
            w0[k] = W_hh[tid * HH + k];
            w1[k] = W_hh[(tid + 100) * HH + k];
        }
        wx2_0 = pack2(W_ih[tid]);
        wx2_1 = pack2(W_ih[tid + 100]);
        bi2_0 = pack2(b_ih[tid]       + b_hh[tid]);
        bi2_1 = pack2(b_ih[tid + 100] + b_hh[tid + 100]);
    }
    // update-phase mapping: thread tid<100 -> unit uu, batches hb..hb+3
    const int uu = tid % 50;
    const int hb = (tid / 50) * 4;
    float c0 = 0.f, c1 = 0.f, c2 = 0.f, c3 = 0.f;

    __syncthreads();

    #pragma unroll 1
    for (int t = 0; t < TT; t++) {
        // ===== gate phase: acc[b] = x*wx + bias + sum_k h[b][k]*w[k] =====
        if (act) {
            ulonglong2 xp0 = *reinterpret_cast<const ulonglong2*>(&x_sh[t][0]);
            ulonglong2 xp1 = *reinterpret_cast<const ulonglong2*>(&x_sh[t][4]);
            u64 a00 = fma2(xp0.x, wx2_0, bi2_0);
            u64 a01 = fma2(xp0.y, wx2_0, bi2_0);
            u64 a02 = fma2(xp1.x, wx2_0, bi2_0);
            u64 a03 = fma2(xp1.y, wx2_0, bi2_0);
            u64 a10 = fma2(xp0.x, wx2_1, bi2_1);
            u64 a11 = fma2(xp0.y, wx2_1, bi2_1);
            u64 a12 = fma2(xp1.x, wx2_1, bi2_1);
            u64 a13 = fma2(xp1.y, wx2_1, bi2_1);
            #pragma unroll
            for (int k = 0; k < HH; k++) {
                ulonglong2 hA = *reinterpret_cast<const ulonglong2*>(&h_sh[k][0]);
                ulonglong2 hB = *reinterpret_cast<const ulonglong2*>(&h_sh[k][4]);
                u64 w0p = pack2(w0[k]);
                u64 w1p = pack2(w1[k]);
                a00 = fma2(hA.x, w0p, a00);
                a01 = fma2(hA.y, w0p, a01);
                a02 = fma2(hB.x, w0p, a02);
                a03 = fma2(hB.y, w0p, a03);
                a10 = fma2(hA.x, w1p, a10);
                a11 = fma2(hA.y, w1p, a11);
                a12 = fma2(hB.x, w1p, a12);
                a13 = fma2(hB.y, w1p, a13);
            }
            ulonglong2 s;
            s.x = a00; s.y = a01; *reinterpret_cast<ulonglong2*>(&g_sh[tid      ][0]) = s;
            s.x = a02; s.y = a03; *reinterpret_cast<ulonglong2*>(&g_sh[tid      ][4]) = s;
            s.x = a10; s.y = a11; *reinterpret_cast<ulonglong2*>(&g_sh[tid + 100][0]) = s;
            s.x = a12; s.y = a13; *reinterpret_cast<ulonglong2*>(&g_sh[tid + 100][4]) = s;
        }
        __syncthreads();

        // ===== cell update: i,f,g,o -> c,h for 4 (unit,batch) cells =====
        if (act) {
            float4 gi = *reinterpret_cast<const float4*>(&g_sh[uu       ][hb]);
            float4 gf = *reinterpret_cast<const float4*>(&g_sh[uu +  50 ][hb]);
            float4 gg = *reinterpret_cast<const float4*>(&g_sh[uu + 100 ][hb]);
            float4 go = *reinterpret_cast<const float4*>(&g_sh[uu + 150 ][hb]);
            float4 hn;
            c0 = sigmoidf_(gf.x) * c0 + sigmoidf_(gi.x) * tanhf_(gg.x); hn.x = sigmoidf_(go.x) * tanhf_(c0);
            c1 = sigmoidf_(gf.y) * c1 + sigmoidf_(gi.y) * tanhf_(gg.y); hn.y = sigmoidf_(go.y) * tanhf_(c1);
            c2 = sigmoidf_(gf.z) * c2 + sigmoidf_(gi.z) * tanhf_(gg.z); hn.z = sigmoidf_(go.z) * tanhf_(c2);
            c3 = sigmoidf_(gf.w) * c3 + sigmoidf_(gi.w) * tanhf_(gg.w); hn.w = sigmoidf_(go.w) * tanhf_(c3);
            *reinterpret_cast<float4*>(&h_sh[uu][hb]) = hn;
        }
        __syncthreads();
    }

    // ===== final FC on h_T: out[b][o] = sum_u h[b][u]*fc_w[o][u] + fc_b[o] =====
    if (tid < NB * 3) {
        int bb = tid / 3, o = tid % 3;
        float s = fc_b[o];
        #pragma unroll
        for (int k = 0; k < HH; k++) s += h_sh[k][bb] * fc_w[o * HH + k];
        out[(size_t)(b0 + bb) * 3 + o] = s;
    }
}

extern "C" void kernel_launch(void* const* d_in, const int* in_sizes, int n_in,
                              void* d_out, int out_size) {
    const float* x    = (const float*)d_in[0];
    const float* W_ih = (const float*)d_in[1];
    const float* W_hh = (const float*)d_in[2];
    const float* b_ih = (const float*)d_in[3];
    const float* b_hh = (const float*)d_in[4];
    const float* fc_w = (const float*)d_in[5];
    const float* fc_b = (const float*)d_in[6];
    lstm_fused<<<2048 / NB, NTHR>>>(x, W_ih, W_hh, b_ih, b_hh, fc_w, fc_b, (float*)d_out);
}